// round 6
// baseline (speedup 1.0000x reference)
#include <cuda_runtime.h>
#include <math.h>

#define BB    16
#define NN    512
#define MM    1024
#define CC    8
#define COUT  64
#define NSLC  4               // n-slices (CTAs) per (b, mtile)
#define NSL   (NN / NSLC)     // 128 n per slice
#define NWARP 8               // warps per main CTA
#define NPW   (NSL / NWARP)   // 16 n per warp
#define MPB   64              // m per tile (2 per lane)
#define TPB   (32 * NWARP)    // 256 threads (main)
#define RTPB  512             // threads (reduce)

__device__ float g_part[BB * (MM / MPB) * NSLC * CC * MPB];  // 8MB scratch

__device__ __forceinline__ float ex2f(float x) {
    float y;
    asm("ex2.approx.ftz.f32 %0, %1;" : "=f"(y) : "f"(x));
    return y;
}
__device__ __forceinline__ unsigned long long pack2(float lo, float hi) {
    unsigned long long r;
    asm("mov.b64 %0, {%1, %2};" : "=l"(r) : "f"(lo), "f"(hi));
    return r;
}
__device__ __forceinline__ void unpack2(unsigned long long v, float& lo, float& hi) {
    asm("mov.b64 {%0, %1}, %2;" : "=f"(lo), "=f"(hi) : "l"(v));
}
__device__ __forceinline__ void ffma2(unsigned long long& d, unsigned long long a, unsigned long long b) {
    asm("fma.rn.f32x2 %0, %1, %2, %0;" : "+l"(d) : "l"(a), "l"(b));
}

// ---------------- main kernel: partial sums over one n-slice ----------------
__global__ __launch_bounds__(TPB)
void convdeepset_main(const float* __restrict__ ci,    // (B,N,1)
                      const float* __restrict__ co,    // (B,N,7)
                      const float* __restrict__ ti,    // (B,M,1)
                      const float* __restrict__ sigma) // (8,)
{
    __shared__ float4      s_ab2[NSL / 2];           // (a0,b0,a1,b1) per local n-pair
    __shared__ ulonglong2  s_cx[NSL * 2];            // packed f32x2 channels
    __shared__ float       s_part[NWARP][CC][MPB];   // 16KB

    const int tid  = threadIdx.x;
    const int w    = tid >> 5;
    const int lane = tid & 31;
    const int blk  = blockIdx.x;
    const int ns   = blk & (NSLC - 1);
    const int mt   = (blk >> 2) & 15;
    const int b    = blk >> 6;
    const int mbase = mt * MPB;
    const int nsbase = ns * NSL;

    // uniform-sigma detection
    const float LOG2E = 1.4426950408889634f;
    float sg0 = sigma[0];
    bool uni = true;
    #pragma unroll
    for (int c = 1; c < CC; c++) uni &= (sigma[c] == sg0);
    const float k2u = -0.5f * LOG2E * expf(-2.0f * sg0);

    // stage this slice's context rows (local index)
    const float* cib = ci + (size_t)b * NN + nsbase;
    const float* cob = co + ((size_t)b * NN + nsbase) * 7;
    float2* s_abf2 = (float2*)s_ab2;
    for (int i = tid; i < NSL; i += TPB) {
        float x = cib[i];
        float2 ab;
        if (uni) { ab.x = k2u * x * x; ab.y = -2.0f * k2u * x; }
        else     { ab.x = x;           ab.y = 0.0f; }
        s_abf2[i] = ab;
        const float* r = cob + i * 7;
        s_cx[2 * i]     = make_ulonglong2(pack2(1.0f, r[0]), pack2(r[1], r[2]));
        s_cx[2 * i + 1] = make_ulonglong2(pack2(r[3], r[4]), pack2(r[5], r[6]));
    }
    __syncthreads();

    const float t0 = ti[(size_t)b * MM + mbase + lane];
    const float t1 = ti[(size_t)b * MM + mbase + lane + 32];

    const int l0 = w * NPW;   // local n start for this warp
    float f0[CC], f1[CC];

    if (uni) {
        unsigned long long x0 = 0ull, x1 = 0ull, x2 = 0ull, x3 = 0ull;
        unsigned long long y0 = 0ull, y1 = 0ull, y2 = 0ull, y3 = 0ull;
        #pragma unroll
        for (int i = 0; i < NPW / 2; i++) {
            const int np = (l0 >> 1) + i;
            const int n  = l0 + 2 * i;
            float4 ab = s_ab2[np];
            float wa0 = ex2f(fmaf(ab.y, t0, ab.x));
            float wb0 = ex2f(fmaf(ab.w, t0, ab.z));
            float wa1 = ex2f(fmaf(ab.y, t1, ab.x));
            float wb1 = ex2f(fmaf(ab.w, t1, ab.z));
            ulonglong2 pa = s_cx[2 * n];
            ulonglong2 qa = s_cx[2 * n + 1];
            ulonglong2 pb = s_cx[2 * n + 2];
            ulonglong2 qb = s_cx[2 * n + 3];
            unsigned long long wa0p = pack2(wa0, wa0);
            unsigned long long wb0p = pack2(wb0, wb0);
            unsigned long long wa1p = pack2(wa1, wa1);
            unsigned long long wb1p = pack2(wb1, wb1);
            ffma2(x0, wa0p, pa.x); ffma2(x1, wa0p, pa.y);
            ffma2(x2, wa0p, qa.x); ffma2(x3, wa0p, qa.y);
            ffma2(x0, wb0p, pb.x); ffma2(x1, wb0p, pb.y);
            ffma2(x2, wb0p, qb.x); ffma2(x3, wb0p, qb.y);
            ffma2(y0, wa1p, pa.x); ffma2(y1, wa1p, pa.y);
            ffma2(y2, wa1p, qa.x); ffma2(y3, wa1p, qa.y);
            ffma2(y0, wb1p, pb.x); ffma2(y1, wb1p, pb.y);
            ffma2(y2, wb1p, qb.x); ffma2(y3, wb1p, qb.y);
        }
        unpack2(x0, f0[0], f0[1]); unpack2(x1, f0[2], f0[3]);
        unpack2(x2, f0[4], f0[5]); unpack2(x3, f0[6], f0[7]);
        unpack2(y0, f1[0], f1[1]); unpack2(y1, f1[2], f1[3]);
        unpack2(y2, f1[4], f1[5]); unpack2(y3, f1[6], f1[7]);
    } else {
        float k2[CC];
        #pragma unroll
        for (int c = 0; c < CC; c++) k2[c] = -0.5f * LOG2E * expf(-2.0f * sigma[c]);
        #pragma unroll
        for (int c = 0; c < CC; c++) { f0[c] = 0.0f; f1[c] = 0.0f; }
        for (int i = 0; i < NPW; i++) {
            int n = l0 + i;
            float x = s_abf2[n].x;
            float d0 = (x - t0) * (x - t0);
            float d1 = (x - t1) * (x - t1);
            const float* cf = (const float*)&s_cx[2 * n];
            #pragma unroll
            for (int c = 0; c < CC; c++) {
                f0[c] += ex2f(d0 * k2[c]) * cf[c];
                f1[c] += ex2f(d1 * k2[c]) * cf[c];
            }
        }
    }

    #pragma unroll
    for (int c = 0; c < CC; c++) {
        s_part[w][c][lane]      = f0[c];
        s_part[w][c][lane + 32] = f1[c];
    }
    __syncthreads();

    // reduce 8 warps -> write 512-float partial block for this CTA
    {
        const int c   = tid >> 5;       // 0..7
        const int mm0 = tid & 31;
        float acc0 = 0.0f, acc1 = 0.0f;
        #pragma unroll
        for (int ww = 0; ww < NWARP; ww++) {
            acc0 += s_part[ww][c][mm0];
            acc1 += s_part[ww][c][mm0 + 32];
        }
        float* outp = g_part + (size_t)blk * (CC * MPB) + c * MPB;
        outp[mm0]      = acc0;
        outp[mm0 + 32] = acc1;
    }
}

// ---------------- reduce kernel: sum slices + normalize + GEMM ----------------
__global__ __launch_bounds__(RTPB)
void convdeepset_reduce(const float* __restrict__ ti,    // (B,M,1)
                        const float* __restrict__ sigma, // (8,)
                        const float* __restrict__ W,     // (64,8)
                        const float* __restrict__ bias,  // (64,)
                        float* __restrict__ out)         // (B,M,64)
{
    __shared__ float s_v[CC][MPB];
    __shared__ float s_dens[MPB];
    __shared__ float s_Wt[CC][COUT];
    __shared__ float s_bias[COUT];

    const int tid = threadIdx.x;
    const int blk = blockIdx.x;         // b*16 + mt
    const int b   = blk >> 4;
    const int mt  = blk & 15;
    const int mbase = mt * MPB;

    if (tid < CC * COUT) {
        int o = tid / CC, c = tid % CC;
        s_Wt[c][o] = W[tid];
    }
    if (tid < COUT) s_bias[tid] = bias[tid];

    const float LOG2E = 1.4426950408889634f;
    float sg0 = sigma[0];
    bool uni = true;
    #pragma unroll
    for (int c = 1; c < CC; c++) uni &= (sigma[c] == sg0);
    const float k2u = -0.5f * LOG2E * expf(-2.0f * sg0);

    // sum 4 slice partials; thread = (c = tid>>6, mm = tid&63)
    {
        const int c  = tid >> 6;
        const int mm = tid & 63;
        const float* base = g_part + (size_t)blk * NSLC * (CC * MPB) + c * MPB + mm;
        float acc = 0.0f;
        #pragma unroll
        for (int s = 0; s < NSLC; s++) acc += base[(size_t)s * (CC * MPB)];
        if (c == 0) s_dens[mm] = acc;
        __syncthreads();

        float tm = ti[(size_t)b * MM + mbase + mm];
        float g  = uni ? ex2f(k2u * tm * tm) : 1.0f;
        float d0 = s_dens[mm] * g;                   // true density
        float inv = g / (d0 + 1e-8f);
        s_v[c][mm] = (c == 0) ? d0 : acc * inv;
        __syncthreads();
    }

    // (8 -> 64) GEMM + bias; thread = (mm = tid>>3, og = tid&7), 8 outputs
    {
        const int mm = tid >> 3;
        const int og = tid & 7;
        float v[CC];
        #pragma unroll
        for (int c = 0; c < CC; c++) v[c] = s_v[c][mm];

        float4 r0 = *(const float4*)&s_bias[og * 8];
        float4 r1 = *(const float4*)&s_bias[og * 8 + 4];
        #pragma unroll
        for (int c = 0; c < CC; c++) {
            float4 w0 = *(const float4*)&s_Wt[c][og * 8];
            float4 w1 = *(const float4*)&s_Wt[c][og * 8 + 4];
            r0.x = fmaf(v[c], w0.x, r0.x);
            r0.y = fmaf(v[c], w0.y, r0.y);
            r0.z = fmaf(v[c], w0.z, r0.z);
            r0.w = fmaf(v[c], w0.w, r0.w);
            r1.x = fmaf(v[c], w1.x, r1.x);
            r1.y = fmaf(v[c], w1.y, r1.y);
            r1.z = fmaf(v[c], w1.z, r1.z);
            r1.w = fmaf(v[c], w1.w, r1.w);
        }
        float4* outp = (float4*)(out + ((size_t)(b * MM + mbase + mm)) * COUT + og * 8);
        outp[0] = r0;
        outp[1] = r1;
    }
}

extern "C" void kernel_launch(void* const* d_in, const int* in_sizes, int n_in,
                              void* d_out, int out_size) {
    const float* ci    = (const float*)d_in[0];
    const float* co    = (const float*)d_in[1];
    const float* ti    = (const float*)d_in[2];
    const float* sigma = (const float*)d_in[3];
    const float* W     = (const float*)d_in[4];
    const float* bias  = (const float*)d_in[5];
    float* out = (float*)d_out;

    convdeepset_main<<<BB * (MM / MPB) * NSLC, TPB>>>(ci, co, ti, sigma);      // 1024 CTAs
    convdeepset_reduce<<<BB * (MM / MPB), RTPB>>>(ti, sigma, W, bias, out);    // 256 CTAs
}